// round 1
// baseline (speedup 1.0000x reference)
#include <cuda_runtime.h>

// ---------------------------------------------------------------------------
// GAT: 3 layers. Strategy:
//   - Build dst-CSR once per launch (count -> scan -> scatter). Reused 3x.
//   - Per layer: GEMM (feat = X @ W, fp32 SIMT, W resident in SMEM),
//                ELR   (el/er per-node attention dots),
//                AGG   (warp-per-node softmax-weighted aggregation, no atomics
//                       in the reduction; softmax max-shift dropped -- exact).
// ---------------------------------------------------------------------------

#define NNODES_MAX 50000
#define NEDGES_MAX 800000

__device__ float g_feat[NNODES_MAX * 128];
__device__ float g_h   [NNODES_MAX * 128];
__device__ float g_el  [NNODES_MAX * 4];
__device__ float g_er  [NNODES_MAX * 4];
__device__ int   g_cnt [NNODES_MAX];          // histogram, then scatter cursor
__device__ int   g_row [NNODES_MAX + 1];      // CSR row offsets
__device__ int   g_bsum[64];                  // scan block sums
__device__ int   g_srcperm[NEDGES_MAX];       // src node per CSR slot

// ------------------------------ CSR build ---------------------------------

__global__ void k_zero_int(int* p, int n) {
    int i = blockIdx.x * blockDim.x + threadIdx.x;
    if (i < n) p[i] = 0;
}

__global__ void k_count(const int* __restrict__ dst, int* __restrict__ cnt, int E) {
    int i = blockIdx.x * blockDim.x + threadIdx.x;
    if (i < E) atomicAdd(&cnt[dst[i]], 1);
}

// per-block exclusive scan of cnt into row; block total to bsum
__global__ void k_scan1(const int* __restrict__ cnt, int* __restrict__ row,
                        int* __restrict__ bsum, int N) {
    __shared__ int sh[1024];
    int tid = threadIdx.x;
    int idx = blockIdx.x * 1024 + tid;
    int c = (idx < N) ? cnt[idx] : 0;
    sh[tid] = c;
    __syncthreads();
    #pragma unroll
    for (int off = 1; off < 1024; off <<= 1) {
        int t = (tid >= off) ? sh[tid - off] : 0;
        __syncthreads();
        sh[tid] += t;
        __syncthreads();
    }
    if (idx < N) row[idx] = sh[tid] - c;          // exclusive
    if (tid == 1023) bsum[blockIdx.x] = sh[1023]; // inclusive total
}

// exclusive scan of block sums (nb <= 64), single block of 64 threads
__global__ void k_scan2(int* __restrict__ bsum, int nb) {
    __shared__ int sh[64];
    int tid = threadIdx.x;
    int v = (tid < nb) ? bsum[tid] : 0;
    sh[tid] = v;
    __syncthreads();
    #pragma unroll
    for (int off = 1; off < 64; off <<= 1) {
        int t = (tid >= off) ? sh[tid - off] : 0;
        __syncthreads();
        sh[tid] += t;
        __syncthreads();
    }
    if (tid < nb) bsum[tid] = sh[tid] - v;        // exclusive offsets
}

// add block offsets; copy into cursor; set row[N]=E
__global__ void k_scan3(int* __restrict__ row, const int* __restrict__ bsum,
                        int* __restrict__ cursor, int N, int E) {
    int idx = blockIdx.x * 1024 + threadIdx.x;
    if (idx < N) {
        int v = row[idx] + bsum[blockIdx.x];
        row[idx] = v;
        cursor[idx] = v;
    }
    if (idx == 0) row[N] = E;
}

__global__ void k_scatter(const int* __restrict__ src, const int* __restrict__ dst,
                          int* __restrict__ cursor, int* __restrict__ srcperm, int E) {
    int i = blockIdx.x * blockDim.x + threadIdx.x;
    if (i < E) {
        int d = dst[i];
        int pos = atomicAdd(&cursor[d], 1);
        srcperm[pos] = src[i];
    }
}

// ------------------------------ GEMM ---------------------------------------
// out[N,C] = X[N,128] @ W[128,C]. Block: 256 threads, 32 rows x C cols.
// W fully resident in SMEM. Register tile: (C/32) rows x 4 cols per thread.

template <int C>
__global__ void k_gemm(const float* __restrict__ X, const float* __restrict__ W,
                       float* __restrict__ out, int N) {
    extern __shared__ float sh[];
    float* Ws = sh;            // 128 * C
    float* Xs = sh + 128 * C;  // 32 * 128
    const int tid = threadIdx.x;
    const int r0 = blockIdx.x * 32;

    // load full W
    #pragma unroll 4
    for (int i = tid; i < 128 * C / 4; i += 256)
        ((float4*)Ws)[i] = ((const float4*)W)[i];
    // load 32 rows of X
    #pragma unroll
    for (int i = tid; i < 32 * 128 / 4; i += 256) {
        int r = i >> 5;           // row in tile (32 float4 per row)
        int c4 = i & 31;
        int row = r0 + r;
        ((float4*)Xs)[i] = (row < N) ? ((const float4*)X)[(size_t)row * 32 + c4]
                                     : make_float4(0.f, 0.f, 0.f, 0.f);
    }
    __syncthreads();

    constexpr int CG = C / 4;     // col groups of 4
    constexpr int RT = C / 32;    // rows per thread (4 for C=128, 2 for C=64)
    const int ci = tid % CG;
    const int ri = tid / CG;

    float acc[RT][4];
    #pragma unroll
    for (int j = 0; j < RT; ++j)
        #pragma unroll
        for (int v = 0; v < 4; ++v) acc[j][v] = 0.f;

    #pragma unroll 8
    for (int k = 0; k < 128; ++k) {
        float4 b4 = ((const float4*)(Ws + k * C))[ci];
        #pragma unroll
        for (int j = 0; j < RT; ++j) {
            float a = Xs[(ri * RT + j) * 128 + k];
            acc[j][0] += a * b4.x;
            acc[j][1] += a * b4.y;
            acc[j][2] += a * b4.z;
            acc[j][3] += a * b4.w;
        }
    }

    #pragma unroll
    for (int j = 0; j < RT; ++j) {
        int row = r0 + ri * RT + j;
        if (row < N) {
            float4 o = make_float4(acc[j][0], acc[j][1], acc[j][2], acc[j][3]);
            ((float4*)(out + (size_t)row * C))[ci] = o;
        }
    }
}

// ------------------------------ EL / ER ------------------------------------
// el[n,h] = sum_d feat[n,h*D+d]*al[h*D+d]; same layout flat dot in segments.
// Warp per node; lane holds V=C/32 elements; reduce within G=D/V lane groups.

template <int C, int H>
__global__ void k_elr(const float* __restrict__ feat, const float* __restrict__ al,
                      const float* __restrict__ ar, float* __restrict__ el,
                      float* __restrict__ er, int N) {
    int warp = (blockIdx.x * blockDim.x + threadIdx.x) >> 5;
    int lane = threadIdx.x & 31;
    if (warp >= N) return;
    constexpr int V = C / 32;
    constexpr int D = C / H;
    constexpr int G = D / V;   // lanes per head

    float pl = 0.f, pr = 0.f;
    #pragma unroll
    for (int v = 0; v < V; ++v) {
        float f = feat[(size_t)warp * C + lane * V + v];
        pl += f * al[lane * V + v];
        pr += f * ar[lane * V + v];
    }
    #pragma unroll
    for (int off = G / 2; off > 0; off >>= 1) {
        pl += __shfl_xor_sync(0xffffffffu, pl, off);
        pr += __shfl_xor_sync(0xffffffffu, pr, off);
    }
    if ((lane % G) == 0) {
        int h = lane / G;
        el[warp * H + h] = pl;
        er[warp * H + h] = pr;
    }
}

// ------------------------------ Aggregation --------------------------------
// Warp per destination node. Softmax without max-shift (exactly equivalent).

template <int C, int H, bool RELU>
__global__ void k_agg(const float* __restrict__ feat, const float* __restrict__ el,
                      const float* __restrict__ er, const int* __restrict__ row,
                      const int* __restrict__ srcperm, const float* __restrict__ bias,
                      float* __restrict__ out, int N) {
    int warp = (blockIdx.x * blockDim.x + threadIdx.x) >> 5;
    int lane = threadIdx.x & 31;
    if (warp >= N) return;
    constexpr int V = C / 32;
    constexpr int D = C / H;
    const int h0 = (lane * V) / D;   // head owned by this lane (V | D)

    float erv = er[warp * H + h0];
    float acc[V];
    #pragma unroll
    for (int v = 0; v < V; ++v) acc[v] = 0.f;
    float denom = 0.f;

    int s = row[warp];
    int send = row[warp + 1];
    for (; s < send; ++s) {
        int sn = srcperm[s];
        float e = el[sn * H + h0] + erv;
        e = (e > 0.f) ? e : 0.2f * e;
        float w = __expf(e);
        denom += w;
        if constexpr (V == 4) {
            float4 f = ((const float4*)(feat + (size_t)sn * C))[lane];
            acc[0] += f.x * w; acc[1] += f.y * w;
            acc[2] += f.z * w; acc[3] += f.w * w;
        } else {
            float2 f = ((const float2*)(feat + (size_t)sn * C))[lane];
            acc[0] += f.x * w; acc[1] += f.y * w;
        }
    }

    float inv = 1.f / fmaxf(denom, 1e-12f);
    float res[V];
    #pragma unroll
    for (int v = 0; v < V; ++v) {
        float o = acc[v] * inv + bias[lane * V + v];
        if (RELU) o = fmaxf(o, 0.f);
        res[v] = o;
    }
    if constexpr (V == 4) {
        ((float4*)(out + (size_t)warp * C))[lane] =
            make_float4(res[0], res[1], res[2], res[3]);
    } else {
        ((float2*)(out + (size_t)warp * C))[lane] = make_float2(res[0], res[1]);
    }
}

// ------------------------------ Host ---------------------------------------

extern "C" void kernel_launch(void* const* d_in, const int* in_sizes, int n_in,
                              void* d_out, int out_size) {
    const float* features = (const float*)d_in[0];
    const int*   src      = (const int*)d_in[1];
    const int*   dst      = (const int*)d_in[2];
    const float* W0  = (const float*)d_in[3];
    const float* al0 = (const float*)d_in[4];
    const float* ar0 = (const float*)d_in[5];
    const float* b0  = (const float*)d_in[6];
    const float* W1  = (const float*)d_in[7];
    const float* al1 = (const float*)d_in[8];
    const float* ar1 = (const float*)d_in[9];
    const float* b1  = (const float*)d_in[10];
    const float* W2  = (const float*)d_in[11];
    const float* al2 = (const float*)d_in[12];
    const float* ar2 = (const float*)d_in[13];
    const float* b2  = (const float*)d_in[14];

    const int N = in_sizes[0] / 128;
    const int E = in_sizes[1];

    float *feat, *h, *el, *er;
    int *cnt, *row, *bsum, *srcperm;
    cudaGetSymbolAddress((void**)&feat, g_feat);
    cudaGetSymbolAddress((void**)&h, g_h);
    cudaGetSymbolAddress((void**)&el, g_el);
    cudaGetSymbolAddress((void**)&er, g_er);
    cudaGetSymbolAddress((void**)&cnt, g_cnt);
    cudaGetSymbolAddress((void**)&row, g_row);
    cudaGetSymbolAddress((void**)&bsum, g_bsum);
    cudaGetSymbolAddress((void**)&srcperm, g_srcperm);

    const int smem128 = (128 * 128 + 32 * 128) * (int)sizeof(float); // 80 KB
    const int smem64  = (128 * 64  + 32 * 128) * (int)sizeof(float); // 48 KB
    cudaFuncSetAttribute(k_gemm<128>, cudaFuncAttributeMaxDynamicSharedMemorySize, smem128);
    cudaFuncSetAttribute(k_gemm<64>,  cudaFuncAttributeMaxDynamicSharedMemorySize, smem64);

    const int nb = (N + 1023) / 1024;

    // ---- CSR build (dst is identical for all three layers) ----
    k_zero_int<<<(N + 255) / 256, 256>>>(cnt, N);
    k_count<<<(E + 255) / 256, 256>>>(dst, cnt, E);
    k_scan1<<<nb, 1024>>>(cnt, row, bsum, N);
    k_scan2<<<1, 64>>>(bsum, nb);
    k_scan3<<<nb, 1024>>>(row, bsum, cnt, N, E);
    k_scatter<<<(E + 255) / 256, 256>>>(src, dst, cnt, srcperm, E);

    const int gemm_blocks = (N + 31) / 32;
    const int node_warp_blocks = (N + 7) / 8;   // 256 threads = 8 warps/block

    // ---- Layer 0: 128 -> 128, H=4, relu ----
    k_gemm<128><<<gemm_blocks, 256, smem128>>>(features, W0, feat, N);
    k_elr<128, 4><<<node_warp_blocks, 256>>>(feat, al0, ar0, el, er, N);
    k_agg<128, 4, true><<<node_warp_blocks, 256>>>(feat, el, er, row, srcperm, b0, h, N);

    // ---- Layer 1: 128 -> 128, H=4, relu ----
    k_gemm<128><<<gemm_blocks, 256, smem128>>>(h, W1, feat, N);
    k_elr<128, 4><<<node_warp_blocks, 256>>>(feat, al1, ar1, el, er, N);
    k_agg<128, 4, true><<<node_warp_blocks, 256>>>(feat, el, er, row, srcperm, b1, h, N);

    // ---- Layer 2: 128 -> 64, H=1, no act ----
    k_gemm<64><<<gemm_blocks, 256, smem64>>>(h, W2, feat, N);
    k_elr<64, 1><<<node_warp_blocks, 256>>>(feat, al2, ar2, el, er, N);
    k_agg<64, 1, false><<<node_warp_blocks, 256>>>(feat, el, er, row, srcperm, b2,
                                                   (float*)d_out, N);
}

// round 2
// speedup vs baseline: 1.1070x; 1.1070x over previous
#include <cuda_runtime.h>

// ---------------------------------------------------------------------------
// GAT, 3 layers. CSR built once; per layer: GEMM (8x8 register tile, swizzled
// k-major A tile in SMEM), ELR (attention dots), AGG (warp-per-node softmax
// aggregation, 4-edge batched, no max-shift -- exact by shift invariance).
// ---------------------------------------------------------------------------

#define NNODES_MAX 50000
#define NEDGES_MAX 800000

__device__ float g_feat[NNODES_MAX * 128];
__device__ float g_h   [NNODES_MAX * 128];
__device__ float g_el  [NNODES_MAX * 4];
__device__ float g_er  [NNODES_MAX * 4];
__device__ int   g_cnt [NNODES_MAX];
__device__ int   g_row [NNODES_MAX + 1];
__device__ int   g_bsum[64];
__device__ int   g_srcperm[NEDGES_MAX];

// ------------------------------ CSR build ---------------------------------

__global__ void k_zero_int(int* p, int n) {
    int i = blockIdx.x * blockDim.x + threadIdx.x;
    if (i < n) p[i] = 0;
}

__global__ void k_count(const int* __restrict__ dst, int* __restrict__ cnt, int E) {
    int i = blockIdx.x * blockDim.x + threadIdx.x;
    if (i < E) atomicAdd(&cnt[dst[i]], 1);
}

__global__ void k_scan1(const int* __restrict__ cnt, int* __restrict__ row,
                        int* __restrict__ bsum, int N) {
    __shared__ int sh[1024];
    int tid = threadIdx.x;
    int idx = blockIdx.x * 1024 + tid;
    int c = (idx < N) ? cnt[idx] : 0;
    sh[tid] = c;
    __syncthreads();
    #pragma unroll
    for (int off = 1; off < 1024; off <<= 1) {
        int t = (tid >= off) ? sh[tid - off] : 0;
        __syncthreads();
        sh[tid] += t;
        __syncthreads();
    }
    if (idx < N) row[idx] = sh[tid] - c;
    if (tid == 1023) bsum[blockIdx.x] = sh[1023];
}

__global__ void k_scan2(int* __restrict__ bsum, int nb) {
    __shared__ int sh[64];
    int tid = threadIdx.x;
    int v = (tid < nb) ? bsum[tid] : 0;
    sh[tid] = v;
    __syncthreads();
    #pragma unroll
    for (int off = 1; off < 64; off <<= 1) {
        int t = (tid >= off) ? sh[tid - off] : 0;
        __syncthreads();
        sh[tid] += t;
        __syncthreads();
    }
    if (tid < nb) bsum[tid] = sh[tid] - v;
}

__global__ void k_scan3(int* __restrict__ row, const int* __restrict__ bsum,
                        int* __restrict__ cursor, int N, int E) {
    int idx = blockIdx.x * 1024 + threadIdx.x;
    if (idx < N) {
        int v = row[idx] + bsum[blockIdx.x];
        row[idx] = v;
        cursor[idx] = v;
    }
    if (idx == 0) row[N] = E;
}

__global__ void k_scatter(const int* __restrict__ src, const int* __restrict__ dst,
                          int* __restrict__ cursor, int* __restrict__ srcperm, int E) {
    int i = blockIdx.x * blockDim.x + threadIdx.x;
    if (i < E) {
        int d = dst[i];
        int pos = atomicAdd(&cursor[d], 1);
        srcperm[pos] = src[i];
    }
}

// ------------------------------ GEMM ---------------------------------------
// out[N,C] = X[N,128] @ W[128,C].
// Block: 128 rows x C cols, THREADS = 2*C (256 / 128). Thread: 8 rows x 8 cols.
// W fully SMEM-resident [128][C]. X chunk transposed to k-major [32][128] with
// XOR swizzle phys_row = row ^ ((k4&7)<<2) -> conflict-free STS and LDS.

template <int C>
__global__ void __launch_bounds__(256, 2)
k_gemm(const float* __restrict__ X, const float* __restrict__ W,
       float* __restrict__ out, int N) {
    extern __shared__ float sh[];
    float* Ws = sh;             // 128 * C
    float* Xs = sh + 128 * C;   // 32 * 128 (k-major, swizzled)

    constexpr int THREADS = 2 * C;
    const int tid = threadIdx.x;
    const int r0 = blockIdx.x * 128;

    constexpr int CT = C / 8;          // col-thread count
    const int ci = tid % CT;
    const int ri = tid / CT;           // 0..15

    // load full W (k-major [128][C])
    #pragma unroll
    for (int i = tid; i < 128 * C / 4; i += THREADS)
        ((float4*)Ws)[i] = ((const float4*)W)[i];

    float acc[8][8];
    #pragma unroll
    for (int i = 0; i < 8; ++i)
        #pragma unroll
        for (int j = 0; j < 8; ++j) acc[i][j] = 0.f;

    #pragma unroll 1
    for (int kc = 0; kc < 4; ++kc) {
        // load & transpose X chunk: 128 rows x 32 k
        #pragma unroll
        for (int i = tid; i < 1024; i += THREADS) {
            int row = i >> 3;
            int k4  = i & 7;
            int grow = r0 + row;
            float4 v = (grow < N)
                ? ((const float4*)X)[(size_t)grow * 32 + kc * 8 + k4]
                : make_float4(0.f, 0.f, 0.f, 0.f);
            int pr = row ^ (k4 << 2);
            Xs[(4 * k4 + 0) * 128 + pr] = v.x;
            Xs[(4 * k4 + 1) * 128 + pr] = v.y;
            Xs[(4 * k4 + 2) * 128 + pr] = v.z;
            Xs[(4 * k4 + 3) * 128 + pr] = v.w;
        }
        __syncthreads();

        #pragma unroll 4
        for (int k = 0; k < 32; ++k) {
            int swz = ((k >> 2) & 7) << 2;
            float4 a0 = *(const float4*)&Xs[k * 128 + ((ri * 8)     ^ swz)];
            float4 a1 = *(const float4*)&Xs[k * 128 + ((ri * 8 + 4) ^ swz)];
            int kk = kc * 32 + k;
            float4 b0 = *(const float4*)&Ws[kk * C + ci * 8];
            float4 b1 = *(const float4*)&Ws[kk * C + ci * 8 + 4];
            float a[8] = {a0.x, a0.y, a0.z, a0.w, a1.x, a1.y, a1.z, a1.w};
            float b[8] = {b0.x, b0.y, b0.z, b0.w, b1.x, b1.y, b1.z, b1.w};
            #pragma unroll
            for (int i = 0; i < 8; ++i)
                #pragma unroll
                for (int j = 0; j < 8; ++j)
                    acc[i][j] += a[i] * b[j];
        }
        __syncthreads();
    }

    #pragma unroll
    for (int i = 0; i < 8; ++i) {
        int row = r0 + ri * 8 + i;
        if (row < N) {
            float4* o = (float4*)(out + (size_t)row * C + ci * 8);
            o[0] = make_float4(acc[i][0], acc[i][1], acc[i][2], acc[i][3]);
            o[1] = make_float4(acc[i][4], acc[i][5], acc[i][6], acc[i][7]);
        }
    }
}

// ------------------------------ EL / ER ------------------------------------

template <int C, int H>
__global__ void k_elr(const float* __restrict__ feat, const float* __restrict__ al,
                      const float* __restrict__ ar, float* __restrict__ el,
                      float* __restrict__ er, int N) {
    int warp = (blockIdx.x * blockDim.x + threadIdx.x) >> 5;
    int lane = threadIdx.x & 31;
    if (warp >= N) return;
    constexpr int V = C / 32;
    constexpr int D = C / H;
    constexpr int G = D / V;

    float pl = 0.f, pr = 0.f;
    #pragma unroll
    for (int v = 0; v < V; ++v) {
        float f = feat[(size_t)warp * C + lane * V + v];
        pl += f * al[lane * V + v];
        pr += f * ar[lane * V + v];
    }
    #pragma unroll
    for (int off = G / 2; off > 0; off >>= 1) {
        pl += __shfl_xor_sync(0xffffffffu, pl, off);
        pr += __shfl_xor_sync(0xffffffffu, pr, off);
    }
    if ((lane % G) == 0) {
        int h = lane / G;
        el[warp * H + h] = pl;
        er[warp * H + h] = pr;
    }
}

// ------------------------------ Aggregation --------------------------------
// Warp per destination node; 4-edge batched loads for MLP.

template <int C, int H, bool RELU>
__global__ void k_agg(const float* __restrict__ feat, const float* __restrict__ el,
                      const float* __restrict__ er, const int* __restrict__ rowp,
                      const int* __restrict__ srcperm, const float* __restrict__ bias,
                      float* __restrict__ out, int N) {
    int warp = (blockIdx.x * blockDim.x + threadIdx.x) >> 5;
    int lane = threadIdx.x & 31;
    if (warp >= N) return;
    constexpr int V = C / 32;
    constexpr int D = C / H;
    const int h0 = (lane * V) / D;

    float erv = er[warp * H + h0];
    float acc[V];
    #pragma unroll
    for (int v = 0; v < V; ++v) acc[v] = 0.f;
    float denom = 0.f;

    int s = rowp[warp];
    const int send = rowp[warp + 1];

    #pragma unroll 1
    for (; s + 4 <= send; s += 4) {
        int a0 = srcperm[s],     a1 = srcperm[s + 1];
        int a2 = srcperm[s + 2], a3 = srcperm[s + 3];
        float e0 = el[a0 * H + h0] + erv;
        float e1 = el[a1 * H + h0] + erv;
        float e2 = el[a2 * H + h0] + erv;
        float e3 = el[a3 * H + h0] + erv;
        e0 = (e0 > 0.f) ? e0 : 0.2f * e0;
        e1 = (e1 > 0.f) ? e1 : 0.2f * e1;
        e2 = (e2 > 0.f) ? e2 : 0.2f * e2;
        e3 = (e3 > 0.f) ? e3 : 0.2f * e3;
        float w0 = __expf(e0), w1 = __expf(e1);
        float w2 = __expf(e2), w3 = __expf(e3);
        denom += (w0 + w1) + (w2 + w3);
        if constexpr (V == 4) {
            float4 f0 = ((const float4*)(feat + (size_t)a0 * C))[lane];
            float4 f1 = ((const float4*)(feat + (size_t)a1 * C))[lane];
            float4 f2 = ((const float4*)(feat + (size_t)a2 * C))[lane];
            float4 f3 = ((const float4*)(feat + (size_t)a3 * C))[lane];
            acc[0] += f0.x * w0 + f1.x * w1 + f2.x * w2 + f3.x * w3;
            acc[1] += f0.y * w0 + f1.y * w1 + f2.y * w2 + f3.y * w3;
            acc[2] += f0.z * w0 + f1.z * w1 + f2.z * w2 + f3.z * w3;
            acc[3] += f0.w * w0 + f1.w * w1 + f2.w * w2 + f3.w * w3;
        } else {
            float2 f0 = ((const float2*)(feat + (size_t)a0 * C))[lane];
            float2 f1 = ((const float2*)(feat + (size_t)a1 * C))[lane];
            float2 f2 = ((const float2*)(feat + (size_t)a2 * C))[lane];
            float2 f3 = ((const float2*)(feat + (size_t)a3 * C))[lane];
            acc[0] += f0.x * w0 + f1.x * w1 + f2.x * w2 + f3.x * w3;
            acc[1] += f0.y * w0 + f1.y * w1 + f2.y * w2 + f3.y * w3;
        }
    }
    for (; s < send; ++s) {
        int sn = srcperm[s];
        float e = el[sn * H + h0] + erv;
        e = (e > 0.f) ? e : 0.2f * e;
        float w = __expf(e);
        denom += w;
        if constexpr (V == 4) {
            float4 f = ((const float4*)(feat + (size_t)sn * C))[lane];
            acc[0] += f.x * w; acc[1] += f.y * w;
            acc[2] += f.z * w; acc[3] += f.w * w;
        } else {
            float2 f = ((const float2*)(feat + (size_t)sn * C))[lane];
            acc[0] += f.x * w; acc[1] += f.y * w;
        }
    }

    float inv = 1.f / fmaxf(denom, 1e-12f);
    float res[V];
    #pragma unroll
    for (int v = 0; v < V; ++v) {
        float o = acc[v] * inv + bias[lane * V + v];
        if (RELU) o = fmaxf(o, 0.f);
        res[v] = o;
    }
    if constexpr (V == 4) {
        ((float4*)(out + (size_t)warp * C))[lane] =
            make_float4(res[0], res[1], res[2], res[3]);
    } else {
        ((float2*)(out + (size_t)warp * C))[lane] = make_float2(res[0], res[1]);
    }
}

// ------------------------------ Host ---------------------------------------

extern "C" void kernel_launch(void* const* d_in, const int* in_sizes, int n_in,
                              void* d_out, int out_size) {
    const float* features = (const float*)d_in[0];
    const int*   src      = (const int*)d_in[1];
    const int*   dst      = (const int*)d_in[2];
    const float* W0  = (const float*)d_in[3];
    const float* al0 = (const float*)d_in[4];
    const float* ar0 = (const float*)d_in[5];
    const float* b0  = (const float*)d_in[6];
    const float* W1  = (const float*)d_in[7];
    const float* al1 = (const float*)d_in[8];
    const float* ar1 = (const float*)d_in[9];
    const float* b1  = (const float*)d_in[10];
    const float* W2  = (const float*)d_in[11];
    const float* al2 = (const float*)d_in[12];
    const float* ar2 = (const float*)d_in[13];
    const float* b2  = (const float*)d_in[14];

    const int N = in_sizes[0] / 128;
    const int E = in_sizes[1];

    float *feat, *h, *el, *er;
    int *cnt, *row, *bsum, *srcperm;
    cudaGetSymbolAddress((void**)&feat, g_feat);
    cudaGetSymbolAddress((void**)&h, g_h);
    cudaGetSymbolAddress((void**)&el, g_el);
    cudaGetSymbolAddress((void**)&er, g_er);
    cudaGetSymbolAddress((void**)&cnt, g_cnt);
    cudaGetSymbolAddress((void**)&row, g_row);
    cudaGetSymbolAddress((void**)&bsum, g_bsum);
    cudaGetSymbolAddress((void**)&srcperm, g_srcperm);

    const int smem128 = (128 * 128 + 32 * 128) * (int)sizeof(float); // 80 KB
    const int smem64  = (128 * 64  + 32 * 128) * (int)sizeof(float); // 48 KB
    cudaFuncSetAttribute(k_gemm<128>, cudaFuncAttributeMaxDynamicSharedMemorySize, smem128);
    cudaFuncSetAttribute(k_gemm<64>,  cudaFuncAttributeMaxDynamicSharedMemorySize, smem64);

    const int nb = (N + 1023) / 1024;
    const int gemm_blocks = (N + 127) / 128;
    const int node_warp_blocks = (N + 7) / 8;

    // CSR build, interleaved so launch #4 is k_gemm<128> (ncu capture target)
    k_zero_int<<<(N + 255) / 256, 256>>>(cnt, N);
    k_count<<<(E + 255) / 256, 256>>>(dst, cnt, E);
    k_scan1<<<nb, 1024>>>(cnt, row, bsum, N);

    // ---- Layer 0 GEMM (launch #4) ----
    k_gemm<128><<<gemm_blocks, 256, smem128>>>(features, W0, feat, N);

    k_scan2<<<1, 64>>>(bsum, nb);
    k_scan3<<<nb, 1024>>>(row, bsum, cnt, N, E);
    k_scatter<<<(E + 255) / 256, 256>>>(src, dst, cnt, srcperm, E);

    // ---- Layer 0 rest ----
    k_elr<128, 4><<<node_warp_blocks, 256>>>(feat, al0, ar0, el, er, N);
    k_agg<128, 4, true><<<node_warp_blocks, 256>>>(feat, el, er, row, srcperm, b0, h, N);

    // ---- Layer 1 ----
    k_gemm<128><<<gemm_blocks, 256, smem128>>>(h, W1, feat, N);
    k_elr<128, 4><<<node_warp_blocks, 256>>>(feat, al1, ar1, el, er, N);
    k_agg<128, 4, true><<<node_warp_blocks, 256>>>(feat, el, er, row, srcperm, b1, h, N);

    // ---- Layer 2 ----
    k_gemm<64><<<gemm_blocks, 128, smem64>>>(h, W2, feat, N);
    k_elr<64, 1><<<node_warp_blocks, 256>>>(feat, al2, ar2, el, er, N);
    k_agg<64, 1, false><<<node_warp_blocks, 256>>>(feat, el, er, row, srcperm, b2,
                                                   (float*)d_out, N);
}